// round 11
// baseline (speedup 1.0000x reference)
#include <cuda_runtime.h>
#include <cuda_fp16.h>
#include <cstdint>

#define E_DIM 256
#define MQ (64*8*128)     /* 65536 query tokens  */
#define MC (2*MQ)         /* 131072 constant rows */

// ---------------- scratch (allocation-free: __device__ globals) ----------------
__device__ __half g_Qh [(size_t)MQ*E_DIM];
__device__ __half g_Kh [(size_t)MC*E_DIM];
__device__ __half g_Vh [(size_t)MC*E_DIM];
__device__ float2 g_W01[(size_t)MQ*4];      // softmax weights per (token, head)
__device__ __half g_Wf[4][E_DIM*E_DIM];

// 128B-row swizzle (rows of 64 fp16 = 128B).
__device__ __forceinline__ int swb(int byte){
  return byte ^ ((byte >> 3) & 0x70);
}

__device__ __forceinline__ void ldm4(uint32_t addr, uint32_t r[4]){
  asm volatile("ldmatrix.sync.aligned.m8n8.x4.shared.b16 {%0,%1,%2,%3}, [%4];\n"
    : "=r"(r[0]),"=r"(r[1]),"=r"(r[2]),"=r"(r[3]) : "r"(addr));
}

__device__ __forceinline__ void mma16816(float c[4], const uint32_t a[4],
                                         uint32_t b0, uint32_t b1){
  asm volatile("mma.sync.aligned.m16n8k16.row.col.f32.f16.f16.f32 "
    "{%0,%1,%2,%3}, {%4,%5,%6,%7}, {%8,%9}, {%0,%1,%2,%3};\n"
    : "+f"(c[0]),"+f"(c[1]),"+f"(c[2]),"+f"(c[3])
    : "r"(a[0]),"r"(a[1]),"r"(a[2]),"r"(a[3]), "r"(b0),"r"(b1));
}

__device__ __forceinline__ void cp_async16(uint32_t dst, const void* src){
  asm volatile("cp.async.cg.shared.global [%0], [%1], 16;" :: "r"(dst), "l"(src));
}
#define CP_COMMIT() asm volatile("cp.async.commit_group;" ::: "memory")
#define CP_WAIT1()  asm volatile("cp.async.wait_group 1;" ::: "memory")
#define CP_WAIT0()  asm volatile("cp.async.wait_group 0;" ::: "memory")

// ---------------- weight fp16 prep ----------------
__global__ void prep_weights(const float* __restrict__ Wq, const float* __restrict__ Wk,
                             const float* __restrict__ Wv, const float* __restrict__ Wo){
  int i = blockIdx.x * blockDim.x + threadIdx.x;   // 0 .. 65535
  const float* src[4] = {Wq, Wk, Wv, Wo};
#pragma unroll
  for (int w = 0; w < 4; w++){
    g_Wf[w][i] = __float2half_rn(src[w][i]);
  }
}

// ---------------- GEMM (templated on phase) ------------------------------------
// fp16 MMA, fp32 acc, 8 warps, BK=64 (4 chunks), 3-stage cp.async B pipeline,
// register-staged A with interleaved convert.
// PHASE 0: jobs = 512 Q-tiles + 2048 KV pairs; tile 128x256 (warp 64x64);
//          A = fp32 input -> fp16 convert.
// PHASE 1: jobs = 1024 O-tiles 128x128 (warp 64x32);
//          A = w0*V0 + w1*V1 fused on the fly (fp16); fp32 output stores.
#define ST_A 16384

template<int PHASE>
__global__ void __launch_bounds__(256, 1)
gemm_all(const float* __restrict__ p, const float* __restrict__ c,
         const float* __restrict__ bq, const float* __restrict__ bk,
         const float* __restrict__ bv, const float* __restrict__ bo,
         float* __restrict__ out)
{
  constexpr int NT = (PHASE == 1) ? 4 : 8;     // n-tiles of 8 per warp
  constexpr int BT = NT / 2;                   // 16-row B tiles per warp
  constexpr int WN = NT * 8;                   // warp n-extent (32 or 64)
  constexpr int BROWS = (PHASE == 1) ? 128 : 256;
  constexpr int ST_B  = BROWS * 128;           // 16KB or 32KB
  constexpr int STAGE = ST_A + ST_B;

  extern __shared__ __align__(128) char smem[];

  const int job = (int)blockIdx.x;
  const float* __restrict__ Xf = nullptr;
  const __half* __restrict__ Wm;
  __half* __restrict__ Yh = nullptr;
  const float* __restrict__ bias;
  size_t mBase; int nBase = 0;
  if (PHASE == 1){
    Wm = g_Wf[3]; bias = bo;
    mBase = (size_t)(job >> 1) * 128;  nBase = (job & 1) * 128;
  } else if (job < 512){
    Xf = p;  Wm = g_Wf[0]; Yh = g_Qh; bias = bq; mBase = (size_t)job * 128;
  } else {
    const int j = job - 512;               // K/V adjacent per M-tile
    Xf = c;  mBase = (size_t)(j >> 1) * 128;
    if ((j & 1) == 0){ Wm = g_Wf[1]; Yh = g_Kh; bias = bk; }
    else             { Wm = g_Wf[2]; Yh = g_Vh; bias = bv; }
  }

  const int tid  = threadIdx.x;
  const int lane = tid & 31;
  const int warp = tid >> 5;
  const int wm   = warp & 1;        // rows wm*64
  const int wn   = warp >> 1;       // cols wn*WN (0..3)

  // ---- async fill of B chunk (16B per cp.async), swizzled ----
  auto issueAsync = [&](int kk, int s){
    char* st = smem + s * STAGE;
#pragma unroll
    for (int i = 0; i < BROWS/32; i++){
      int id = tid + i*256;
      int row = id >> 3, c8 = (id & 7) * 8;
      uint32_t d = (uint32_t)__cvta_generic_to_shared(st + ST_A + swb(row*128 + c8*2));
      cp_async16(d, Wm + (size_t)(nBase + row)*E_DIM + kk + c8);
    }
    CP_COMMIT();
  };

  // ---- register-staged A (both phases), 2 halves per chunk ----
  float4 ra[4];                 // PHASE 0: 4 float4 slots per half
  uint4  rv0[2], rv1[2];        // PHASE 1: 2 slots (v0,v1) per half
  float2 rw[2];

  auto loadAh = [&](int kk, int h){
    if (PHASE == 0){
#pragma unroll
      for (int i = 0; i < 4; i++){
        int id = tid + i*256 + h*1024;
        int row = id >> 4, c4 = id & 15;
        ra[i] = *reinterpret_cast<const float4*>(Xf + (mBase + row)*E_DIM + kk + c4*4);
      }
    } else {
      const int hd = kk >> 6;   // head for this K-chunk
#pragma unroll
      for (int i = 0; i < 2; i++){
        int id = tid + i*256 + h*512;
        int row = id >> 3, c8 = (id & 7) * 8;
        size_t tok = mBase + row;
        rv0[i] = *reinterpret_cast<const uint4*>(g_Vh + (size_t)(2*tok  )*E_DIM + kk + c8);
        rv1[i] = *reinterpret_cast<const uint4*>(g_Vh + (size_t)(2*tok+1)*E_DIM + kk + c8);
        rw[i]  = g_W01[tok*4 + hd];
      }
    }
  };
  auto storeAh = [&](int s, int h){
    char* st = smem + s * STAGE;
    if (PHASE == 0){
#pragma unroll
      for (int i = 0; i < 4; i++){
        int id = tid + i*256 + h*1024;
        int row = id >> 4, c4 = id & 15;
        float4 v = ra[i];
        __half2 h0 = __float22half2_rn(make_float2(v.x, v.y));
        __half2 h1 = __float22half2_rn(make_float2(v.z, v.w));
        int b0 = swb(row*128 + c4*8);
        *reinterpret_cast<__half2*>(st + b0)     = h0;
        *reinterpret_cast<__half2*>(st + b0 + 4) = h1;
      }
    } else {
#pragma unroll
      for (int i = 0; i < 2; i++){
        int id = tid + i*256 + h*512;
        int row = id >> 3, c8 = (id & 7) * 8;
        const float w0 = rw[i].x, w1 = rw[i].y;
        const __half2* a = reinterpret_cast<const __half2*>(&rv0[i]);
        const __half2* b = reinterpret_cast<const __half2*>(&rv1[i]);
        uint4 o;
        __half2* oh = reinterpret_cast<__half2*>(&o);
#pragma unroll
        for (int j = 0; j < 4; j++){
          float2 af = __half22float2(a[j]);
          float2 bf = __half22float2(b[j]);
          oh[j] = __floats2half2_rn(w0*af.x + w1*bf.x, w0*af.y + w1*bf.y);
        }
        *reinterpret_cast<uint4*>(st + swb(row*128 + c8*2)) = o;
      }
    }
  };

  float acc[4][NT][4];
#pragma unroll
  for (int i=0;i<4;i++)
#pragma unroll
    for (int j=0;j<NT;j++)
#pragma unroll
      for (int k=0;k<4;k++) acc[i][j][k] = 0.f;

  // prologue: B chunks 0,1 in flight; A chunk 0 staged
  issueAsync(0, 0);
  loadAh(0, 0); storeAh(0, 0);
  loadAh(0, 1); storeAh(0, 1);
  issueAsync(64, 1);

  for (int kc = 0; kc < 4; kc++){
    const int cur = kc % 3;
    if (kc < 3) CP_WAIT1(); else CP_WAIT0();
    __syncthreads();

    if (kc < 2) issueAsync((kc+2)*64, (kc+2) % 3);
    const int ns = (kc+1) % 3;               // A stage for next chunk

    char* sAc = smem + cur * STAGE;
    char* sBc = sAc + ST_A;
    const bool preA = (kc < 3);

#pragma unroll
    for (int ks2 = 0; ks2 < 4; ks2++){
      const int ks = ks2*16;
      uint32_t Af[4][4], Bf[BT][4];
#pragma unroll
      for (int mt=0; mt<4; mt++){
        int row = wm*64 + mt*16 + (lane & 7) + ((lane & 8) ? 8 : 0);
        int col = ks + ((lane & 16) ? 8 : 0);
        ldm4((uint32_t)__cvta_generic_to_shared(sAc + swb(row*128 + col*2)), Af[mt]);
      }
#pragma unroll
      for (int bt=0; bt<BT; bt++){
        int row = wn*WN + bt*16 + (lane & 7) + ((lane & 8) ? 8 : 0);
        int col = ks + ((lane & 16) ? 8 : 0);
        ldm4((uint32_t)__cvta_generic_to_shared(sBc + swb(row*128 + col*2)), Bf[bt]);
      }
#pragma unroll
      for (int mt=0; mt<4; mt++)
#pragma unroll
        for (int nt=0; nt<NT; nt++){
          const int bt = nt >> 1, od = nt & 1;
          mma16816(acc[mt][nt], Af[mt], Bf[bt][od], Bf[bt][2+od]);
        }
      // interleave next-chunk A stage between ks phases
      if (preA){
        if      (ks2 == 0){ loadAh((kc+1)*64, 0); }
        else if (ks2 == 1){ storeAh(ns, 0); loadAh((kc+1)*64, 1); }
        else if (ks2 == 2){ storeAh(ns, 1); }
      }
    }
  }

  // epilogue: +bias; fp16 stores (Q/K/V) or fp32 (final out)
#pragma unroll
  for (int mt=0; mt<4; mt++){
#pragma unroll
    for (int nt=0; nt<NT; nt++){
      size_t m = mBase + wm*64 + mt*16 + (lane>>2);
      int    n = nBase + wn*WN + nt*8 + (lane&3)*2;
      float b0 = bias[n], b1 = bias[n+1];
      float* a = acc[mt][nt];
      if (PHASE == 1){
        *reinterpret_cast<float2*>(out + m*E_DIM + n)     = make_float2(a[0]+b0, a[1]+b1);
        *reinterpret_cast<float2*>(out + (m+8)*E_DIM + n) = make_float2(a[2]+b0, a[3]+b1);
      } else {
        *reinterpret_cast<__half2*>(Yh + m*E_DIM + n)     = __floats2half2_rn(a[0]+b0, a[1]+b1);
        *reinterpret_cast<__half2*>(Yh + (m+8)*E_DIM + n) = __floats2half2_rn(a[2]+b0, a[3]+b1);
      }
    }
  }
}

// ---------------- attention-lite: softmax weights only -------------------------
__device__ __forceinline__ float dot8(uint4 a, uint4 b){
  const __half2* ah = reinterpret_cast<const __half2*>(&a);
  const __half2* bh = reinterpret_cast<const __half2*>(&b);
  float s = 0.f;
#pragma unroll
  for (int i = 0; i < 4; i++){
    float2 af = __half22float2(ah[i]);
    float2 bf = __half22float2(bh[i]);
    s += af.x*bf.x + af.y*bf.y;
  }
  return s;
}

__global__ void __launch_bounds__(256)
attn_lite()
{
  const int gw   = (blockIdx.x * 256 + threadIdx.x) >> 5;  // token id
  const int lane = threadIdx.x & 31;                        // 8 lanes per head

  const uint4* q  = reinterpret_cast<const uint4*>(g_Qh + (size_t)gw*E_DIM);
  const uint4* k0 = reinterpret_cast<const uint4*>(g_Kh + (size_t)(2*gw  )*E_DIM);
  const uint4* k1 = reinterpret_cast<const uint4*>(g_Kh + (size_t)(2*gw+1)*E_DIM);

  uint4 qa = q[lane];
  float s0 = dot8(qa, k0[lane]);
  float s1 = dot8(qa, k1[lane]);

#pragma unroll
  for (int off = 4; off > 0; off >>= 1){            // reduce within 8-lane head group
    s0 += __shfl_xor_sync(0xffffffffu, s0, off);
    s1 += __shfl_xor_sync(0xffffffffu, s1, off);
  }
  s0 *= 0.125f;  s1 *= 0.125f;                       // 1/sqrt(D), D=64
  float mx = fmaxf(s0, s1);
  float e0 = __expf(s0 - mx), e1 = __expf(s1 - mx);
  float inv = 1.0f / (e0 + e1);

  if ((lane & 7) == 0){
    g_W01[(size_t)gw*4 + (lane >> 3)] = make_float2(e0*inv, e1*inv);
  }
}

// ---------------- launch ----------------
extern "C" void kernel_launch(void* const* d_in, const int* in_sizes, int n_in,
                              void* d_out, int out_size)
{
  const float* p  = (const float*)d_in[0];  // (B,S,A,1,E)  -> [65536,256]
  const float* c  = (const float*)d_in[1];  // (B,S,A,2,E)  -> [131072,256]
  const float* Wq = (const float*)d_in[2];
  const float* bq = (const float*)d_in[3];
  const float* Wk = (const float*)d_in[4];
  const float* bk = (const float*)d_in[5];
  const float* Wv = (const float*)d_in[6];
  const float* bv = (const float*)d_in[7];
  const float* Wo = (const float*)d_in[8];
  const float* bo = (const float*)d_in[9];
  float* out = (float*)d_out;

  const int smem0 = 3 * (ST_A + 256*128);   // 144KB
  const int smem1 = 3 * (ST_A + 128*128);   // 96KB
  cudaFuncSetAttribute(gemm_all<0>, cudaFuncAttributeMaxDynamicSharedMemorySize, smem0);
  cudaFuncSetAttribute(gemm_all<1>, cudaFuncAttributeMaxDynamicSharedMemorySize, smem1);

  prep_weights<<<256, 256>>>(Wq, Wk, Wv, Wo);
  // merged Q/K/V: 512 Q jobs + 2048 KV jobs (128x256 tiles)
  gemm_all<0><<<2560, 256, smem0>>>(p, c, bq, bk, bv, bo, out);
  attn_lite<<<MQ/8, 256>>>();
  // out = (w0*V0 + w1*V1) @ Wo^T + bo, fused A; 1024 jobs (128x128 tiles)
  gemm_all<1><<<1024, 256, smem1>>>(p, c, bq, bk, bv, bo, out);
}